// round 1
// baseline (speedup 1.0000x reference)
#include <cuda_runtime.h>

// Ball query (radius=2, nsample=32) + gather(xyz/2, feat) + concat.
// Shapes: candidate_pts (B=2, 128, 10, 3) -> 2560 queries
//         tgt_pts_xyz (2, 16384, 3), tgt_deep_feat_pts (2, 16384, 32)
// Output: (2, 128, 10, 32, 35) fp32.

#define KNN 32
#define WARPS_PER_BLOCK 8
#define THREADS (WARPS_PER_BLOCK * 32)

__global__ void ball_query_gather_kernel(
    const float* __restrict__ q_xyz,   // (Q, 3) flattened queries
    const float* __restrict__ pts,     // (B, N, 3)
    const float* __restrict__ feat,    // (B, N, F)
    float* __restrict__ out,           // (Q, KNN, 3+F)
    int Q, int N, int F, int Qper)     // Qper = Q / B
{
    const int gwarp = (int)((blockIdx.x * (unsigned)blockDim.x + threadIdx.x) >> 5);
    const int lane  = (int)(threadIdx.x & 31u);
    if (gwarp >= Q) return;

    const int wslot = (int)(threadIdx.x >> 5);
    __shared__ int sidx[WARPS_PER_BLOCK][KNN];
    int* my = sidx[wslot];

    const int b = gwarp / Qper;
    const float* __restrict__ p = pts  + (size_t)b * N * 3;
    const float* __restrict__ f = feat + (size_t)b * N * F;

    const float qx = q_xyz[gwarp * 3 + 0];
    const float qy = q_xyz[gwarp * 3 + 1];
    const float qz = q_xyz[gwarp * 3 + 2];
    const float qq = qx * qx + qy * qy + qz * qz;

    // --- scan phase: ordered compaction of first KNN in-radius indices ---
    int count = 0;
    for (int n0 = 0; n0 < N && count < KNN; n0 += 32) {
        const int n = n0 + lane;
        const float px = p[n * 3 + 0];
        const float py = p[n * 3 + 1];
        const float pz = p[n * 3 + 2];
        // same algebraic form as the reference: |q|^2 - 2 q.x + |x|^2
        const float dot = qx * px + qy * py + qz * pz;
        const float xx  = px * px + py * py + pz * pz;
        const float d2  = qq - 2.0f * dot + xx;
        const bool ok = (d2 <= 4.0f);  // reference excludes d2 > r^2
        const unsigned m = __ballot_sync(0xffffffffu, ok);
        const int pre = __popc(m & ((1u << lane) - 1u));
        if (ok) {
            const int slot = count + pre;
            if (slot < KNN) my[slot] = n;
        }
        count += __popc(m);
    }
    __syncwarp();

    // --- degenerate fill (practically never taken with these inputs) ---
    if (count < KNN) {
        const int first = (count > 0) ? my[0] : (N - 1);  // JAX OOB gather clamps
        for (int s = count + lane; s < KNN; s += 32) my[s] = first;
        __syncwarp();
    }

    // --- gather + concat, fully coalesced stores ---
    const int CH = 3 + F;  // 35
    float* __restrict__ o = out + (size_t)gwarp * KNN * CH;
    const int total = KNN * CH;  // 1120
    for (int pos = lane; pos < total; pos += 32) {
        const int k = pos / CH;
        const int j = pos - k * CH;
        const int idx = my[k];
        float v;
        if (j < 3) {
            v = p[idx * 3 + j] * 0.5f;       // nn_xyz / D_RADIUS (radius = 2)
        } else {
            v = f[idx * F + (j - 3)];
        }
        o[pos] = v;
    }
}

extern "C" void kernel_launch(void* const* d_in, const int* in_sizes, int n_in,
                              void* d_out, int out_size) {
    const float* candidate_pts = (const float*)d_in[0];  // (B,128,10,3)
    // d_in[1] = src_keypts — unused by the reference
    const float* tgt_pts_xyz   = (const float*)d_in[2];  // (B,N,3)
    const float* tgt_feat      = (const float*)d_in[3];  // (B,N,F)
    float* out = (float*)d_out;

    const int B = 2;
    const int Q = in_sizes[0] / 3;           // 2560
    const int N = in_sizes[2] / (3 * B);     // 16384
    const int F = in_sizes[3] / (N * B);     // 32
    const int Qper = Q / B;                  // 1280

    const int warps_needed = Q;
    const int blocks = (warps_needed * 32 + THREADS - 1) / THREADS;
    ball_query_gather_kernel<<<blocks, THREADS>>>(
        candidate_pts, tgt_pts_xyz, tgt_feat, out, Q, N, F, Qper);
}

// round 2
// speedup vs baseline: 3.8641x; 3.8641x over previous
#include <cuda_runtime.h>

// Ball query (radius=2, nsample=32) + gather(xyz/2, feat) + concat.
// One 256-thread block per query point: block-wide ordered compaction of the
// first KNN in-radius indices (8x shorter worst-case scan than 1 warp/query),
// then warp-per-neighbor coalesced gather.

#define KNN 32
#define THREADS 256
#define NWARP (THREADS / 32)

__global__ __launch_bounds__(THREADS)
void ball_query_gather_kernel(
    const float* __restrict__ q_xyz,   // (Q, 3)
    const float* __restrict__ pts,     // (B, N, 3)
    const float* __restrict__ feat,    // (B, N, 32)
    float* __restrict__ out,           // (Q, KNN, 35)
    int Q, int N, int Qper)
{
    const int q    = blockIdx.x;
    const int tid  = threadIdx.x;
    const int warp = tid >> 5;
    const int lane = tid & 31;

    __shared__ int      s_idx[KNN];
    __shared__ unsigned s_mask[NWARP];

    const int b = q / Qper;
    const float* __restrict__ p = pts  + (size_t)b * N * 3;
    const float* __restrict__ f = feat + (size_t)b * N * 32;

    const float qx = q_xyz[q * 3 + 0];
    const float qy = q_xyz[q * 3 + 1];
    const float qz = q_xyz[q * 3 + 2];
    const float qq = qx * qx + qy * qy + qz * qz;

    // --- block-wide ordered compaction of first KNN in-radius indices ---
    int count = 0;
    for (int n0 = 0; n0 < N && count < KNN; n0 += THREADS) {
        const int n  = n0 + tid;
        const int nc = (n < N) ? n : (N - 1);
        const float px = p[nc * 3 + 0];
        const float py = p[nc * 3 + 1];
        const float pz = p[nc * 3 + 2];
        // same algebraic form as the reference: |q|^2 - 2 q.x + |x|^2
        const float dot = qx * px + qy * py + qz * pz;
        const float xx  = px * px + py * py + pz * pz;
        const float d2  = qq - 2.0f * dot + xx;
        const bool ok = (n < N) && (d2 <= 4.0f);

        const unsigned m = __ballot_sync(0xffffffffu, ok);
        if (lane == 0) s_mask[warp] = m;
        __syncthreads();

        int base = count, total = 0;
        #pragma unroll
        for (int w = 0; w < NWARP; ++w) {
            const int c = __popc(s_mask[w]);
            if (w < warp) base += c;
            total += c;
        }
        if (ok) {
            const int slot = base + __popc(m & ((1u << lane) - 1u));
            if (slot < KNN) s_idx[slot] = n;
        }
        count += total;
        __syncthreads();   // protects s_mask reuse AND publishes s_idx
    }

    // --- degenerate fill (statistically never taken with these inputs) ---
    if (count < KNN) {
        const int first = (count > 0) ? s_idx[0] : (N - 1);  // JAX clamps OOB gather
        if (tid >= count && tid < KNN) s_idx[tid] = first;
        __syncthreads();
    }

    // --- gather + concat: one warp per neighbor row, coalesced ---
    float* __restrict__ o = out + (size_t)q * KNN * 35;
    #pragma unroll
    for (int k = warp; k < KNN; k += NWARP) {
        const int idx = s_idx[k];
        const float v = f[idx * 32 + lane];          // one 128B coalesced load
        o[k * 35 + 3 + lane] = v;
        if (lane < 3)
            o[k * 35 + lane] = p[idx * 3 + lane] * 0.5f;  // nn_xyz / D_RADIUS
    }
}

extern "C" void kernel_launch(void* const* d_in, const int* in_sizes, int n_in,
                              void* d_out, int out_size) {
    const float* candidate_pts = (const float*)d_in[0];  // (B,128,10,3)
    const float* tgt_pts_xyz   = (const float*)d_in[2];  // (B,N,3)
    const float* tgt_feat      = (const float*)d_in[3];  // (B,N,32)
    float* out = (float*)d_out;

    const int B = 2;
    const int Q = in_sizes[0] / 3;           // 2560
    const int N = in_sizes[2] / (3 * B);     // 16384
    const int Qper = Q / B;                  // 1280

    ball_query_gather_kernel<<<Q, THREADS>>>(
        candidate_pts, tgt_pts_xyz, tgt_feat, out, Q, N, Qper);
}

// round 3
// speedup vs baseline: 4.7140x; 1.2200x over previous
#include <cuda_runtime.h>

// Ball query (radius=2, nsample=32) + gather(xyz/2, feat) + concat.
// One 1024-thread block per query: block-wide ordered compaction of the first
// KNN in-radius indices (worst case 16 iterations over N=16384), single
// barrier per iteration (double-buffered ballot masks, shfl cross-warp
// prefix), then single-pass warp-per-neighbor coalesced gather.

#define KNN 32
#define THREADS 1024
#define NWARP (THREADS / 32)   // 32

__global__ __launch_bounds__(THREADS)
void ball_query_gather_kernel(
    const float* __restrict__ q_xyz,   // (Q, 3)
    const float* __restrict__ pts,     // (B, N, 3)
    const float* __restrict__ feat,    // (B, N, 32)
    float* __restrict__ out,           // (Q, KNN, 35)
    int Q, int N, int Qper)
{
    const int q    = blockIdx.x;
    const int tid  = threadIdx.x;
    const int warp = tid >> 5;
    const int lane = tid & 31;

    __shared__ int      s_idx[KNN];
    __shared__ unsigned s_mask[2][NWARP];

    const int b = q / Qper;
    const float* __restrict__ p = pts  + (size_t)b * N * 3;
    const float* __restrict__ f = feat + (size_t)b * N * 32;

    const float qx = q_xyz[q * 3 + 0];
    const float qy = q_xyz[q * 3 + 1];
    const float qz = q_xyz[q * 3 + 2];
    const float qq = qx * qx + qy * qy + qz * qz;

    // --- block-wide ordered compaction of first KNN in-radius indices ---
    int count = 0;
    int buf = 0;
    for (int n0 = 0; n0 < N && count < KNN; n0 += THREADS, buf ^= 1) {
        const int n  = n0 + tid;
        const int nc = (n < N) ? n : (N - 1);
        const float px = p[nc * 3 + 0];
        const float py = p[nc * 3 + 1];
        const float pz = p[nc * 3 + 2];
        // same algebraic form as the reference: |q|^2 - 2 q.x + |x|^2
        const float dot = qx * px + qy * py + qz * pz;
        const float xx  = px * px + py * py + pz * pz;
        const float d2  = qq - 2.0f * dot + xx;
        const bool ok = (n < N) && (d2 <= 4.0f);

        const unsigned m = __ballot_sync(0xffffffffu, ok);
        if (lane == 0) s_mask[buf][warp] = m;
        __syncthreads();   // the only barrier per iteration

        // cross-warp exclusive prefix of per-warp hit counts (shfl scan)
        const int cnt = __popc(s_mask[buf][lane]);   // lane w holds warp w's count
        int inc = cnt;
        #pragma unroll
        for (int off = 1; off < 32; off <<= 1) {
            const int v = __shfl_up_sync(0xffffffffu, inc, off);
            if (lane >= off) inc += v;
        }
        const int total = __shfl_sync(0xffffffffu, inc, 31);
        const int base  = __shfl_sync(0xffffffffu, inc - cnt, warp);

        if (ok) {
            const int slot = count + base + __popc(m & ((1u << lane) - 1u));
            if (slot < KNN) s_idx[slot] = n;
        }
        count += total;
    }
    __syncthreads();   // publish s_idx

    // --- degenerate fill (statistically never taken with these inputs) ---
    if (count < KNN) {
        const int first = (count > 0) ? s_idx[0] : (N - 1);  // JAX clamps OOB gather
        if (tid >= count && tid < KNN) s_idx[tid] = first;
        __syncthreads();
    }

    // --- gather + concat: warp k owns neighbor k, single pass, coalesced ---
    if (warp < KNN) {
        const int idx = s_idx[warp];
        float* __restrict__ o = out + (size_t)q * KNN * 35 + warp * 35;
        o[3 + lane] = f[idx * 32 + lane];              // one 128B coalesced load
        if (lane < 3)
            o[lane] = p[idx * 3 + lane] * 0.5f;        // nn_xyz / D_RADIUS
    }
}

extern "C" void kernel_launch(void* const* d_in, const int* in_sizes, int n_in,
                              void* d_out, int out_size) {
    const float* candidate_pts = (const float*)d_in[0];  // (B,128,10,3)
    const float* tgt_pts_xyz   = (const float*)d_in[2];  // (B,N,3)
    const float* tgt_feat      = (const float*)d_in[3];  // (B,N,32)
    float* out = (float*)d_out;

    const int B = 2;
    const int Q = in_sizes[0] / 3;           // 2560
    const int N = in_sizes[2] / (3 * B);     // 16384
    const int Qper = Q / B;                  // 1280

    ball_query_gather_kernel<<<Q, THREADS>>>(
        candidate_pts, tgt_pts_xyz, tgt_feat, out, Q, N, Qper);
}

// round 4
// speedup vs baseline: 5.9025x; 1.2521x over previous
#include <cuda_runtime.h>

// Ball query (radius=2, nsample=32) + gather(xyz/2, feat) + concat.
// One 256-thread block per query. Chunk 0 scans 256 points (1 pt/thread) —
// enough for the median query. Subsequent chunks scan 1024 points
// (4 pts/thread via float4 loads). Ordered block compaction: warp shfl scan +
// double-buffered per-warp totals in smem (one barrier per chunk).

#define KNN 32
#define THREADS 256
#define NWARP (THREADS / 32)   // 8

// Ordered compaction of this chunk's hits into s_idx. ok_bits bit j set means
// point (base_ptidx + j) is in radius. Returns updated block-wide count.
__device__ __forceinline__ int compact_write(
    unsigned ok_bits, int base_ptidx,
    int warp, int lane, int buf,
    unsigned s_wcnt[2][NWARP], int* s_idx, int count)
{
    const int c = __popc(ok_bits);
    // warp-inclusive scan of per-thread hit counts
    int inc = c;
    #pragma unroll
    for (int off = 1; off < 32; off <<= 1) {
        const int v = __shfl_up_sync(0xffffffffu, inc, off);
        if (lane >= off) inc += v;
    }
    if (lane == 31) s_wcnt[buf][warp] = (unsigned)inc;   // warp total
    __syncthreads();                                     // only barrier/chunk

    int wbase = 0, total = 0;
    #pragma unroll
    for (int w = 0; w < NWARP; ++w) {
        const int t = (int)s_wcnt[buf][w];
        if (w < warp) wbase += t;
        total += t;
    }
    int slot = count + wbase + (inc - c);
    unsigned bits = ok_bits;
    while (bits && slot < KNN) {
        const int j = __ffs(bits) - 1;
        bits &= bits - 1;
        s_idx[slot++] = base_ptidx + j;
    }
    return count + total;
}

__global__ __launch_bounds__(THREADS)
void ball_query_gather_kernel(
    const float* __restrict__ q_xyz,   // (Q, 3)
    const float* __restrict__ pts,     // (B, N, 3)
    const float* __restrict__ feat,    // (B, N, 32)
    float* __restrict__ out,           // (Q, KNN, 35)
    int Q, int N, int Qper)
{
    const int q    = blockIdx.x;
    const int tid  = threadIdx.x;
    const int warp = tid >> 5;
    const int lane = tid & 31;

    __shared__ int      s_idx[KNN];
    __shared__ unsigned s_wcnt[2][NWARP];

    const int b = q / Qper;
    const float* __restrict__ p = pts  + (size_t)b * N * 3;
    const float* __restrict__ f = feat + (size_t)b * N * 32;

    const float qx = q_xyz[q * 3 + 0];
    const float qy = q_xyz[q * 3 + 1];
    const float qz = q_xyz[q * 3 + 2];
    const float qq = qx * qx + qy * qy + qz * qz;

    // --- chunk 0: points [0, 256), 1 point per thread ---
    int count;
    {
        const int n = tid;                       // always < N (N = 16384)
        const float px = p[n * 3 + 0];
        const float py = p[n * 3 + 1];
        const float pz = p[n * 3 + 2];
        const float dot = qx * px + qy * py + qz * pz;
        const float xx  = px * px + py * py + pz * pz;
        const float d2  = qq - 2.0f * dot + xx;  // reference's algebraic form
        const unsigned bit = (d2 <= 4.0f) ? 1u : 0u;
        count = compact_write(bit, n, warp, lane, 0, s_wcnt, s_idx, 0);
    }

    // --- chunks of 1024 points, 4 points per thread (3x float4 loads) ---
    int buf = 1;
    for (int n0 = THREADS; n0 < N && count < KNN; n0 += 4 * THREADS, buf ^= 1) {
        const int base4 = n0 + 4 * tid;          // multiple of 4
        unsigned bits = 0;
        if (base4 + 4 <= N) {                    // N % 4 == 0 -> no straddle
            const float4* pv = reinterpret_cast<const float4*>(p + (size_t)base4 * 3);
            const float4 v0 = pv[0];
            const float4 v1 = pv[1];
            const float4 v2 = pv[2];
            const float x0 = v0.x, y0 = v0.y, z0 = v0.z;
            const float x1 = v0.w, y1 = v1.x, z1 = v1.y;
            const float x2 = v1.z, y2 = v1.w, z2 = v2.x;
            const float x3 = v2.y, y3 = v2.z, z3 = v2.w;
            const float d0 = qq - 2.0f * (qx*x0 + qy*y0 + qz*z0) + (x0*x0 + y0*y0 + z0*z0);
            const float d1 = qq - 2.0f * (qx*x1 + qy*y1 + qz*z1) + (x1*x1 + y1*y1 + z1*z1);
            const float d2_ = qq - 2.0f * (qx*x2 + qy*y2 + qz*z2) + (x2*x2 + y2*y2 + z2*z2);
            const float d3 = qq - 2.0f * (qx*x3 + qy*y3 + qz*z3) + (x3*x3 + y3*y3 + z3*z3);
            bits  = (d0 <= 4.0f ? 1u : 0u)
                  | (d1 <= 4.0f ? 2u : 0u)
                  | (d2_ <= 4.0f ? 4u : 0u)
                  | (d3 <= 4.0f ? 8u : 0u);
        }
        count = compact_write(bits, base4, warp, lane, buf, s_wcnt, s_idx, count);
    }
    __syncthreads();   // publish s_idx

    // --- degenerate fill (statistically never taken with these inputs) ---
    if (count < KNN) {
        const int first = (count > 0) ? s_idx[0] : (N - 1);  // JAX clamps OOB gather
        if (tid >= count && tid < KNN) s_idx[tid] = first;
        __syncthreads();
    }

    // --- gather + concat: 8 warps x 4 independent neighbor rows, coalesced ---
    float* __restrict__ o = out + (size_t)q * KNN * 35;
    int   kidx[KNN / NWARP];
    #pragma unroll
    for (int i = 0; i < KNN / NWARP; ++i)
        kidx[i] = s_idx[warp * (KNN / NWARP) + i];
    #pragma unroll
    for (int i = 0; i < KNN / NWARP; ++i) {
        const int k   = warp * (KNN / NWARP) + i;
        const int idx = kidx[i];
        o[k * 35 + 3 + lane] = f[idx * 32 + lane];        // 128B coalesced
        if (lane < 3)
            o[k * 35 + lane] = p[idx * 3 + lane] * 0.5f;  // nn_xyz / D_RADIUS
    }
}

extern "C" void kernel_launch(void* const* d_in, const int* in_sizes, int n_in,
                              void* d_out, int out_size) {
    const float* candidate_pts = (const float*)d_in[0];  // (B,128,10,3)
    const float* tgt_pts_xyz   = (const float*)d_in[2];  // (B,N,3)
    const float* tgt_feat      = (const float*)d_in[3];  // (B,N,32)
    float* out = (float*)d_out;

    const int B = 2;
    const int Q = in_sizes[0] / 3;           // 2560
    const int N = in_sizes[2] / (3 * B);     // 16384
    const int Qper = Q / B;                  // 1280

    ball_query_gather_kernel<<<Q, THREADS>>>(
        candidate_pts, tgt_pts_xyz, tgt_feat, out, Q, N, Qper);
}